// round 1
// baseline (speedup 1.0000x reference)
#include <cuda_runtime.h>

#define HW 65536
#define IMG 256

// Scratch: hidden[4][384][256][256] fp32 = 402MB (static __device__ global, allowed)
static __device__ float g_hidden[(size_t)4 * 384 * HW];

// ---------------------------------------------------------------------------
// Kernel 1: 1x1 conv 64 -> 384:  hidden[b,o,p] = sum_c w1[o,c] * x[b,c,p]
// CTA tile: 128 o x 128 pixels, K=64 in one slab. 256 threads, 8o x 8p each.
// ---------------------------------------------------------------------------
__global__ __launch_bounds__(256) void conv1x1_kernel(const float* __restrict__ x,
                                                      const float* __restrict__ w1) {
    extern __shared__ float sm1[];
    float* xs = sm1;            // [64][128]
    float* ws = sm1 + 64 * 128; // [128][64]
    const int t = threadIdx.x;
    const long P0 = (long)blockIdx.x * 128;
    const int b = (int)(P0 >> 16);
    const int hw0 = (int)(P0 & 65535);
    const int o0 = blockIdx.y * 128;

    const float* xb = x + ((long)b * 64) * HW + hw0;
#pragma unroll
    for (int r = 0; r < 8; r++) {
        int idx = t + r * 256;        // float4 id, 2048 total (64 rows x 32 f4)
        int c = idx >> 5;
        int p4 = idx & 31;
        float4 v = *(const float4*)(xb + (long)c * HW + p4 * 4);
        *(float4*)(xs + c * 128 + p4 * 4) = v;
    }
#pragma unroll
    for (int r = 0; r < 8; r++) {
        int idx = t + r * 256;        // 128 rows x 16 f4
        int o = idx >> 4;
        int c4 = idx & 15;
        *(float4*)(ws + o * 64 + c4 * 4) =
            *(const float4*)(w1 + (long)(o0 + o) * 64 + c4 * 4);
    }
    __syncthreads();

    const int to = t >> 4, tp = t & 15;
    const int oo = to * 8, pp = tp * 8;
    float acc[8][8];
#pragma unroll
    for (int i = 0; i < 8; i++)
#pragma unroll
        for (int j = 0; j < 8; j++) acc[i][j] = 0.f;

#pragma unroll 4
    for (int k = 0; k < 64; k++) {
        float a0 = ws[(oo + 0) * 64 + k];
        float a1 = ws[(oo + 1) * 64 + k];
        float a2 = ws[(oo + 2) * 64 + k];
        float a3 = ws[(oo + 3) * 64 + k];
        float a4 = ws[(oo + 4) * 64 + k];
        float a5 = ws[(oo + 5) * 64 + k];
        float a6 = ws[(oo + 6) * 64 + k];
        float a7 = ws[(oo + 7) * 64 + k];
        float4 b0 = *(const float4*)(xs + k * 128 + pp);
        float4 b1 = *(const float4*)(xs + k * 128 + pp + 4);
        float bv[8] = {b0.x, b0.y, b0.z, b0.w, b1.x, b1.y, b1.z, b1.w};
        float av[8] = {a0, a1, a2, a3, a4, a5, a6, a7};
#pragma unroll
        for (int i = 0; i < 8; i++)
#pragma unroll
            for (int j = 0; j < 8; j++) acc[i][j] += av[i] * bv[j];
    }

    float* hb = g_hidden + ((long)b * 384 + o0) * HW + hw0;
#pragma unroll
    for (int i = 0; i < 8; i++) {
        float4 v0 = make_float4(acc[i][0], acc[i][1], acc[i][2], acc[i][3]);
        float4 v1 = make_float4(acc[i][4], acc[i][5], acc[i][6], acc[i][7]);
        *(float4*)(hb + (long)(oo + i) * HW + pp) = v0;
        *(float4*)(hb + (long)(oo + i) * HW + pp + 4) = v1;
    }
}

// ---------------------------------------------------------------------------
// Kernel 2: per 8x8 patch — depthwise 3x3 (with zero-pad halo) -> q,k,v;
// 8x8 circular conv q (*) k; LayerNorm over 128 channels; gate by v;
// projection 128 -> 64; coalesced writeout. One CTA per patch (4096 CTAs).
// ---------------------------------------------------------------------------
// smem layout (floats):
//   bufQ    @0      [128][64]  (8192)   -- overlaid later by gatedT/projbuf
//   bufK    @8192   [128][72]  (9216)   -- row stride 9 for rotated loads
//   gatedT  @0      [64][132]  (8448)   (overlay of bufQ/bufK region)
//   projbuf @8448   [64][68]   (4352)   (overlay, disjoint from gatedT)
//   convout @17408  [128][64]  (8192)
//   hs      @25600  [12][100]  (1200)
//   wdws    @26800  [12][9]    (108)
//   psum    @26908  [4][64]    (256)
//   psq     @27164  [4][64]    (256)
// total = 27420 floats = 109680 bytes
#define S_BUFK 8192
#define S_GATED 0
#define S_PROJ 8448
#define S_CONVO 17408
#define S_HS 25600
#define S_WDW 26800
#define S_PSUM 26908
#define S_PSQ 27164
#define SMEM2_FLOATS 27420

__global__ __launch_bounds__(256) void fsas_kernel(const float* __restrict__ wdw,
                                                   const float* __restrict__ w_out,
                                                   const float* __restrict__ lnw,
                                                   const float* __restrict__ lnb,
                                                   float* __restrict__ out) {
    extern __shared__ float sm[];
    float* bufQ = sm;
    float* bufK = sm + S_BUFK;
    float* gatedT = sm + S_GATED;
    float* projbuf = sm + S_PROJ;
    float* convout = sm + S_CONVO;
    float* hs = sm + S_HS;
    float* wdws = sm + S_WDW;
    float* psum = sm + S_PSUM;
    float* psq = sm + S_PSQ;

    const int t = threadIdx.x;
    const int pid = blockIdx.x;          // 0..4095
    const int b = pid >> 10;
    const int ph = (pid >> 5) & 31;
    const int pw = pid & 31;
    const int y0 = ph * 8, x0 = pw * 8;
    const int lane = t >> 6;             // 0..3 (channel lane)
    const int pix = t & 63;              // 0..63
    const int pa = pix >> 3, pb = pix & 7;

    float vreg[32];                      // v-channel values owned by this thread

    const float* hbase = g_hidden + (long)b * 384 * HW;

    // ---- Phase 1: depthwise conv, 12 planes (4q,4k,4v) per iteration ----
#pragma unroll 1
    for (int cb = 0; cb < 32; cb++) {
        if (t < 108) {
            int pl = t / 9, tap = t % 9;
            int ch = (pl >> 2) * 128 + cb * 4 + (pl & 3);
            wdws[t] = wdw[ch * 9 + tap];
        }
        for (int l = t; l < 1200; l += 256) {
            int pl = l / 100, pp2 = l % 100;
            int ch = (pl >> 2) * 128 + cb * 4 + (pl & 3);
            int py = y0 + pp2 / 10 - 1;
            int px = x0 + pp2 % 10 - 1;
            float v = 0.f;
            if (py >= 0 && py < IMG && px >= 0 && px < IMG)
                v = hbase[(long)ch * HW + py * IMG + px];
            hs[l] = v;
        }
        __syncthreads();

        float q = 0.f, k = 0.f, vv = 0.f;
        const float* hq = hs + lane * 100;
        const float* hk = hs + (4 + lane) * 100;
        const float* hv = hs + (8 + lane) * 100;
        const float* wq = wdws + lane * 9;
        const float* wk = wdws + (4 + lane) * 9;
        const float* wv = wdws + (8 + lane) * 9;
#pragma unroll
        for (int ky = 0; ky < 3; ky++)
#pragma unroll
            for (int kx = 0; kx < 3; kx++) {
                int hofs = (pa + ky) * 10 + pb + kx;
                int wofs = ky * 3 + kx;
                q += hq[hofs] * wq[wofs];
                k += hk[hofs] * wk[wofs];
                vv += hv[hofs] * wv[wofs];
            }
        int c = cb * 4 + lane;
        bufQ[c * 64 + pix] = q;
        bufK[c * 72 + pa * 9 + pb] = k;
        vreg[cb] = vv;
        __syncthreads();
    }

    // ---- Phase 2: 8x8 circular conv per channel (direct, reg rotation) ----
#pragma unroll 1
    for (int r = 0; r < 4; r++) {
        int task = r * 256 + t;          // 1024 tasks = 128 ch x 8 rows
        int c = task >> 3;
        int a = task & 7;
        const float* bq = bufQ + c * 64;
        const float* bk = bufK + c * 72;
        float acc[8];
#pragma unroll
        for (int bb = 0; bb < 8; bb++) acc[bb] = 0.f;
#pragma unroll
        for (int i = 0; i < 8; i++) {
            float4 q0 = *(const float4*)(bq + i * 8);
            float4 q1 = *(const float4*)(bq + i * 8 + 4);
            float qr[8] = {q0.x, q0.y, q0.z, q0.w, q1.x, q1.y, q1.z, q1.w};
            int ka = (a - i) & 7;
            const float* kr = bk + ka * 9;
            float kk[8];
#pragma unroll
            for (int m = 0; m < 8; m++) kk[m] = kr[m];
#pragma unroll
            for (int j = 0; j < 8; j++)
#pragma unroll
                for (int bb = 0; bb < 8; bb++) acc[bb] += qr[j] * kk[(bb - j) & 7];
        }
        float* co = convout + c * 64 + a * 8;
        *(float4*)(co) = make_float4(acc[0], acc[1], acc[2], acc[3]);
        *(float4*)(co + 4) = make_float4(acc[4], acc[5], acc[6], acc[7]);
    }
    __syncthreads();

    // ---- Phase 3: LayerNorm over 128 channels, gate by v ----
    {
        float s = 0.f, s2 = 0.f;
#pragma unroll 1
        for (int cb = 0; cb < 32; cb++) {
            float v = convout[(cb * 4 + lane) * 64 + pix];
            s += v;
            s2 += v * v;
        }
        psum[lane * 64 + pix] = s;
        psq[lane * 64 + pix] = s2;
    }
    __syncthreads();
    {
        float mu = (psum[pix] + psum[64 + pix] + psum[128 + pix] + psum[192 + pix]) *
                   (1.f / 128.f);
        float ex2 = (psq[pix] + psq[64 + pix] + psq[128 + pix] + psq[192 + pix]) *
                    (1.f / 128.f);
        float var = ex2 - mu * mu;
        float rstd = rsqrtf(var + 1e-5f);
#pragma unroll 1
        for (int cb = 0; cb < 32; cb++) {
            int c = cb * 4 + lane;
            float g = (convout[c * 64 + pix] - mu) * rstd * __ldg(lnw + c) + __ldg(lnb + c);
            gatedT[pix * 132 + c] = g * vreg[cb];   // overlays bufQ/bufK (done)
        }
    }
    __syncthreads();

    // ---- Phase 4: projection 128 -> 64 ----
    {
        int o = t >> 2;       // 0..63
        int pl = t & 3;       // pixel interleave lane
        float acc[16];
#pragma unroll
        for (int pp2 = 0; pp2 < 16; pp2++) acc[pp2] = 0.f;
        const float4* wrow = (const float4*)(w_out) + o * 32;
#pragma unroll 1
        for (int cq = 0; cq < 32; cq++) {
            float4 w4 = __ldg(wrow + cq);
#pragma unroll
            for (int pp2 = 0; pp2 < 16; pp2++) {
                int p = pp2 * 4 + pl;
                float4 g4 = *(const float4*)(gatedT + p * 132 + cq * 4);
                acc[pp2] += w4.x * g4.x + w4.y * g4.y + w4.z * g4.z + w4.w * g4.w;
            }
        }
#pragma unroll
        for (int pp2 = 0; pp2 < 16; pp2++)
            projbuf[o * 68 + pp2 * 4 + pl] = acc[pp2];
    }
    __syncthreads();

    // ---- Phase 5: coalesced writeout ----
    {
        int o2 = t >> 2;
        int part = t & 3;
        float* ob = out + ((long)(b * 64 + o2) * IMG + y0) * IMG + x0;
#pragma unroll
        for (int ry = 0; ry < 2; ry++) {
            int y = part * 2 + ry;
            float4 v0 = *(const float4*)(projbuf + o2 * 68 + y * 8);
            float4 v1 = *(const float4*)(projbuf + o2 * 68 + y * 8 + 4);
            *(float4*)(ob + y * IMG) = v0;
            *(float4*)(ob + y * IMG + 4) = v1;
        }
    }
}

// ---------------------------------------------------------------------------
extern "C" void kernel_launch(void* const* d_in, const int* in_sizes, int n_in,
                              void* d_out, int out_size) {
    const float* x = (const float*)d_in[0];
    const float* w1 = (const float*)d_in[1];
    const float* wdw = (const float*)d_in[2];
    const float* wout = (const float*)d_in[3];
    const float* lnw = (const float*)d_in[4];
    const float* lnb = (const float*)d_in[5];
    float* out = (float*)d_out;

    // attribute sets are not stream ops; safe under graph capture
    cudaFuncSetAttribute(conv1x1_kernel, cudaFuncAttributeMaxDynamicSharedMemorySize,
                         64 * 128 * 4 + 128 * 64 * 4);
    cudaFuncSetAttribute(fsas_kernel, cudaFuncAttributeMaxDynamicSharedMemorySize,
                         SMEM2_FLOATS * 4);

    conv1x1_kernel<<<dim3(2048, 3, 1), 256, 64 * 128 * 4 + 128 * 64 * 4>>>(x, w1);
    fsas_kernel<<<4096, 256, SMEM2_FLOATS * 4>>>(wdw, wout, lnw, lnb, out);
}

// round 2
// speedup vs baseline: 1.9606x; 1.9606x over previous
#include <cuda_runtime.h>

#define HW 65536
#define IMG 256

// Scratch (static __device__ globals, allowed):
// hidden[4][384][256][256] fp32 = 402MB
// qkv patched layout: [b][patch(1024)][384][64] fp32 = 402MB
static __device__ float g_hidden[(size_t)4 * 384 * HW];
static __device__ float g_qkv[(size_t)4 * 1024 * 384 * 64];

// ---------------------------------------------------------------------------
// Kernel 1: 1x1 conv 64 -> 384:  hidden[b,o,p] = sum_c w1[o,c] * x[b,c,p]
// CTA tile: 128 o x 128 pixels, K=64 in one slab. 256 threads, 8o x 8p each.
// ---------------------------------------------------------------------------
__global__ __launch_bounds__(256) void conv1x1_kernel(const float* __restrict__ x,
                                                      const float* __restrict__ w1) {
    extern __shared__ float sm1[];
    float* xs = sm1;            // [64][128]
    float* ws = sm1 + 64 * 128; // [128][64]
    const int t = threadIdx.x;
    const long P0 = (long)blockIdx.x * 128;
    const int b = (int)(P0 >> 16);
    const int hw0 = (int)(P0 & 65535);
    const int o0 = blockIdx.y * 128;

    const float* xb = x + ((long)b * 64) * HW + hw0;
#pragma unroll
    for (int r = 0; r < 8; r++) {
        int idx = t + r * 256;        // float4 id, 2048 total (64 rows x 32 f4)
        int c = idx >> 5;
        int p4 = idx & 31;
        float4 v = *(const float4*)(xb + (long)c * HW + p4 * 4);
        *(float4*)(xs + c * 128 + p4 * 4) = v;
    }
#pragma unroll
    for (int r = 0; r < 8; r++) {
        int idx = t + r * 256;        // 128 rows x 16 f4
        int o = idx >> 4;
        int c4 = idx & 15;
        *(float4*)(ws + o * 64 + c4 * 4) =
            *(const float4*)(w1 + (long)(o0 + o) * 64 + c4 * 4);
    }
    __syncthreads();

    const int to = t >> 4, tp = t & 15;
    const int oo = to * 8, pp = tp * 8;
    float acc[8][8];
#pragma unroll
    for (int i = 0; i < 8; i++)
#pragma unroll
        for (int j = 0; j < 8; j++) acc[i][j] = 0.f;

#pragma unroll 4
    for (int k = 0; k < 64; k++) {
        float av[8];
#pragma unroll
        for (int i = 0; i < 8; i++) av[i] = ws[(oo + i) * 64 + k];
        float4 b0 = *(const float4*)(xs + k * 128 + pp);
        float4 b1 = *(const float4*)(xs + k * 128 + pp + 4);
        float bv[8] = {b0.x, b0.y, b0.z, b0.w, b1.x, b1.y, b1.z, b1.w};
#pragma unroll
        for (int i = 0; i < 8; i++)
#pragma unroll
            for (int j = 0; j < 8; j++) acc[i][j] += av[i] * bv[j];
    }

    float* hb = g_hidden + ((long)b * 384 + o0) * HW + hw0;
#pragma unroll
    for (int i = 0; i < 8; i++) {
        float4 v0 = make_float4(acc[i][0], acc[i][1], acc[i][2], acc[i][3]);
        float4 v1 = make_float4(acc[i][4], acc[i][5], acc[i][6], acc[i][7]);
        *(float4*)(hb + (long)(oo + i) * HW + pp) = v0;
        *(float4*)(hb + (long)(oo + i) * HW + pp + 4) = v1;
    }
}

// ---------------------------------------------------------------------------
// Kernel 2: depthwise 3x3 (zero pad), full plane, 64x64 tiles + halo.
// Writes patched layout: g_qkv[((b*1024+pg)*384 + ch)*64 + inner]
// grid: (16 tiles, 384 ch, 4 b), 256 threads.
// smem: 66 rows x stride 68 = 4488 floats (~17.9KB)
// ---------------------------------------------------------------------------
__global__ __launch_bounds__(256) void dw3x3_kernel(const float* __restrict__ wdw) {
    __shared__ float smh[66 * 68];
    const int t = threadIdx.x;
    const int tix = blockIdx.x;
    const int ch = blockIdx.y;
    const int b = blockIdx.z;
    const int ty = tix >> 2, tx = tix & 3;
    const int y0 = ty * 64, x0 = tx * 64;

    const float* src = g_hidden + (long)(b * 384 + ch) * HW;
    for (int l = t; l < 66 * 66; l += 256) {
        int r = l / 66, c = l - r * 66;
        int y = y0 + r - 1, x = x0 + c - 1;
        float v = 0.f;
        if ((unsigned)y < 256u && (unsigned)x < 256u) v = src[y * IMG + x];
        smh[r * 68 + c] = v;
    }
    float w[9];
#pragma unroll
    for (int i = 0; i < 9; i++) w[i] = __ldg(wdw + ch * 9 + i);
    __syncthreads();

#pragma unroll 4
    for (int i = 0; i < 16; i++) {
        int L = t + i * 256;             // 4096 outputs, patched linear order
        int p = L >> 6, inner = L & 63;
        int tpy = p >> 3, tpx = p & 7;
        int iy = inner >> 3, ix = inner & 7;
        int y = tpy * 8 + iy, x = tpx * 8 + ix;   // tile-local
        float acc = 0.f;
#pragma unroll
        for (int ky = 0; ky < 3; ky++)
#pragma unroll
            for (int kx = 0; kx < 3; kx++)
                acc += smh[(y + ky) * 68 + (x + kx)] * w[ky * 3 + kx];
        int pg = (ty * 8 + tpy) * 32 + (tx * 8 + tpx);
        g_qkv[((long)(b * 1024 + pg) * 384 + ch) * 64 + inner] = acc;
    }
}

// ---------------------------------------------------------------------------
// Kernel 3: per 8x8 patch — 8x8 circular conv q (*) k; LayerNorm over 128 ch;
// gate by v; projection 128 -> 64; coalesced writeout. One CTA per patch.
// smem layout (floats):
//   bufQ    @0      [128][64]  (8192)   -- overlaid later by gatedT/projbuf
//   bufK    @8192   [128][72]  (9216)   -- row stride 9 for rotated loads
//   gatedT  @0      [64][132]  (8448)   (overlay)
//   projbuf @8448   [64][68]   (4352)   (overlay, disjoint from gatedT)
//   convout @17408  [128][64]  (8192)
//   psum    @25600  [4][64]    (256)
//   psq     @25856  [4][64]    (256)
// total = 26112 floats = 104448 bytes
#define S_BUFK 8192
#define S_GATED 0
#define S_PROJ 8448
#define S_CONVO 17408
#define S_PSUM 25600
#define S_PSQ 25856
#define SMEM2_FLOATS 26112

__global__ __launch_bounds__(256) void fsas2_kernel(const float* __restrict__ w_out,
                                                    const float* __restrict__ lnw,
                                                    const float* __restrict__ lnb,
                                                    float* __restrict__ out) {
    extern __shared__ float sm[];
    float* bufQ = sm;
    float* bufK = sm + S_BUFK;
    float* gatedT = sm + S_GATED;
    float* projbuf = sm + S_PROJ;
    float* convout = sm + S_CONVO;
    float* psum = sm + S_PSUM;
    float* psq = sm + S_PSQ;

    const int t = threadIdx.x;
    const int pid = blockIdx.x;          // 0..4095
    const int b = pid >> 10;
    const int patch = pid & 1023;
    const int ph = patch >> 5;
    const int pw = patch & 31;
    const int y0 = ph * 8, x0 = pw * 8;
    const int lane = t >> 6;             // 0..3 (channel lane)
    const int pix = t & 63;              // 0..63

    const float* base = g_qkv + (long)pid * 384 * 64;

    // ---- prefetch v to registers (coalesced; hides latency behind copies) ----
    float vreg[32];
#pragma unroll
    for (int cb = 0; cb < 32; cb++)
        vreg[cb] = base[(256 + cb * 4 + lane) * 64 + pix];

    // ---- load q (straight 32KB copy) and k (scatter to 9-stride rows) ----
#pragma unroll
    for (int r = 0; r < 8; r++) {
        int idx = t + r * 256;           // 2048 float4
        ((float4*)bufQ)[idx] = ((const float4*)base)[idx];
    }
#pragma unroll
    for (int r = 0; r < 8; r++) {
        int idx = t + r * 256;           // 2048 float4 (128ch x 16 f4)
        float4 v = ((const float4*)(base + 8192))[idx];
        int c = idx >> 4;
        int word = (idx & 15) * 4;       // 0..60
        int row = word >> 3, col = word & 7;   // col in {0,4}
        float* dk = bufK + c * 72 + row * 9 + col;
        dk[0] = v.x; dk[1] = v.y; dk[2] = v.z; dk[3] = v.w;
    }
    __syncthreads();

    // ---- Phase 2: 8x8 circular conv per channel (direct, reg rotation) ----
#pragma unroll 1
    for (int r = 0; r < 4; r++) {
        int task = r * 256 + t;          // 1024 tasks = 128 ch x 8 rows
        int c = task >> 3;
        int a = task & 7;
        const float* bq = bufQ + c * 64;
        const float* bk = bufK + c * 72;
        float acc[8];
#pragma unroll
        for (int bb = 0; bb < 8; bb++) acc[bb] = 0.f;
#pragma unroll
        for (int i = 0; i < 8; i++) {
            float4 q0 = *(const float4*)(bq + i * 8);
            float4 q1 = *(const float4*)(bq + i * 8 + 4);
            float qr[8] = {q0.x, q0.y, q0.z, q0.w, q1.x, q1.y, q1.z, q1.w};
            int ka = (a - i) & 7;
            const float* kr = bk + ka * 9;
            float kk[8];
#pragma unroll
            for (int m = 0; m < 8; m++) kk[m] = kr[m];
#pragma unroll
            for (int j = 0; j < 8; j++)
#pragma unroll
                for (int bb = 0; bb < 8; bb++) acc[bb] += qr[j] * kk[(bb - j) & 7];
        }
        float* co = convout + c * 64 + a * 8;
        *(float4*)(co) = make_float4(acc[0], acc[1], acc[2], acc[3]);
        *(float4*)(co + 4) = make_float4(acc[4], acc[5], acc[6], acc[7]);
    }
    __syncthreads();

    // ---- Phase 3: LayerNorm over 128 channels, gate by v ----
    {
        float s = 0.f, s2 = 0.f;
#pragma unroll 1
        for (int cb = 0; cb < 32; cb++) {
            float v = convout[(cb * 4 + lane) * 64 + pix];
            s += v;
            s2 += v * v;
        }
        psum[lane * 64 + pix] = s;
        psq[lane * 64 + pix] = s2;
    }
    __syncthreads();
    {
        float mu = (psum[pix] + psum[64 + pix] + psum[128 + pix] + psum[192 + pix]) *
                   (1.f / 128.f);
        float ex2 = (psq[pix] + psq[64 + pix] + psq[128 + pix] + psq[192 + pix]) *
                    (1.f / 128.f);
        float var = ex2 - mu * mu;
        float rstd = rsqrtf(var + 1e-5f);
#pragma unroll 1
        for (int cb = 0; cb < 32; cb++) {
            int c = cb * 4 + lane;
            float g = (convout[c * 64 + pix] - mu) * rstd * __ldg(lnw + c) + __ldg(lnb + c);
            gatedT[pix * 132 + c] = g * vreg[cb];   // overlays bufQ/bufK (done)
        }
    }
    __syncthreads();

    // ---- Phase 4: projection 128 -> 64 ----
    {
        int o = t >> 2;       // 0..63
        int pl = t & 3;       // pixel interleave lane
        float acc[16];
#pragma unroll
        for (int pp2 = 0; pp2 < 16; pp2++) acc[pp2] = 0.f;
        const float4* wrow = (const float4*)(w_out) + o * 32;
#pragma unroll 1
        for (int cq = 0; cq < 32; cq++) {
            float4 w4 = __ldg(wrow + cq);
#pragma unroll
            for (int pp2 = 0; pp2 < 16; pp2++) {
                int p = pp2 * 4 + pl;
                float4 g4 = *(const float4*)(gatedT + p * 132 + cq * 4);
                acc[pp2] += w4.x * g4.x + w4.y * g4.y + w4.z * g4.z + w4.w * g4.w;
            }
        }
#pragma unroll
        for (int pp2 = 0; pp2 < 16; pp2++)
            projbuf[o * 68 + pp2 * 4 + pl] = acc[pp2];
    }
    __syncthreads();

    // ---- Phase 5: coalesced writeout ----
    {
        int o2 = t >> 2;
        int part = t & 3;
        float* ob = out + ((long)(b * 64 + o2) * IMG + y0) * IMG + x0;
#pragma unroll
        for (int ry = 0; ry < 2; ry++) {
            int y = part * 2 + ry;
            float4 v0 = *(const float4*)(projbuf + o2 * 68 + y * 8);
            float4 v1 = *(const float4*)(projbuf + o2 * 68 + y * 8 + 4);
            *(float4*)(ob + y * IMG) = v0;
            *(float4*)(ob + y * IMG + 4) = v1;
        }
    }
}

// ---------------------------------------------------------------------------
extern "C" void kernel_launch(void* const* d_in, const int* in_sizes, int n_in,
                              void* d_out, int out_size) {
    const float* x = (const float*)d_in[0];
    const float* w1 = (const float*)d_in[1];
    const float* wdw = (const float*)d_in[2];
    const float* wout = (const float*)d_in[3];
    const float* lnw = (const float*)d_in[4];
    const float* lnb = (const float*)d_in[5];
    float* out = (float*)d_out;

    cudaFuncSetAttribute(conv1x1_kernel, cudaFuncAttributeMaxDynamicSharedMemorySize,
                         64 * 128 * 4 + 128 * 64 * 4);
    cudaFuncSetAttribute(fsas2_kernel, cudaFuncAttributeMaxDynamicSharedMemorySize,
                         SMEM2_FLOATS * 4);

    conv1x1_kernel<<<dim3(2048, 3, 1), 256, 64 * 128 * 4 + 128 * 64 * 4>>>(x, w1);
    dw3x3_kernel<<<dim3(16, 384, 4), 256>>>(wdw);
    fsas2_kernel<<<4096, 256, SMEM2_FLOATS * 4>>>(wout, lnw, lnb, out);
}

// round 3
// speedup vs baseline: 2.1964x; 1.1203x over previous
#include <cuda_runtime.h>

#define HW 65536
#define IMG 256

// Scratch (static __device__ globals, allowed):
static __device__ float g_hidden[(size_t)4 * 384 * HW];
static __device__ float g_qkv[(size_t)4 * 1024 * 384 * 64];

// ---------------------------------------------------------------------------
// Kernel 1: 1x1 conv 64 -> 384 (unchanged from R1; 300us, fma 54.6%)
// ---------------------------------------------------------------------------
__global__ __launch_bounds__(256) void conv1x1_kernel(const float* __restrict__ x,
                                                      const float* __restrict__ w1) {
    extern __shared__ float sm1[];
    float* xs = sm1;            // [64][128]
    float* ws = sm1 + 64 * 128; // [128][64]
    const int t = threadIdx.x;
    const long P0 = (long)blockIdx.x * 128;
    const int b = (int)(P0 >> 16);
    const int hw0 = (int)(P0 & 65535);
    const int o0 = blockIdx.y * 128;

    const float* xb = x + ((long)b * 64) * HW + hw0;
#pragma unroll
    for (int r = 0; r < 8; r++) {
        int idx = t + r * 256;
        int c = idx >> 5;
        int p4 = idx & 31;
        float4 v = *(const float4*)(xb + (long)c * HW + p4 * 4);
        *(float4*)(xs + c * 128 + p4 * 4) = v;
    }
#pragma unroll
    for (int r = 0; r < 8; r++) {
        int idx = t + r * 256;
        int o = idx >> 4;
        int c4 = idx & 15;
        *(float4*)(ws + o * 64 + c4 * 4) =
            *(const float4*)(w1 + (long)(o0 + o) * 64 + c4 * 4);
    }
    __syncthreads();

    const int to = t >> 4, tp = t & 15;
    const int oo = to * 8, pp = tp * 8;
    float acc[8][8];
#pragma unroll
    for (int i = 0; i < 8; i++)
#pragma unroll
        for (int j = 0; j < 8; j++) acc[i][j] = 0.f;

#pragma unroll 4
    for (int k = 0; k < 64; k++) {
        float av[8];
#pragma unroll
        for (int i = 0; i < 8; i++) av[i] = ws[(oo + i) * 64 + k];
        float4 b0 = *(const float4*)(xs + k * 128 + pp);
        float4 b1 = *(const float4*)(xs + k * 128 + pp + 4);
        float bv[8] = {b0.x, b0.y, b0.z, b0.w, b1.x, b1.y, b1.z, b1.w};
#pragma unroll
        for (int i = 0; i < 8; i++)
#pragma unroll
            for (int j = 0; j < 8; j++) acc[i][j] += av[i] * bv[j];
    }

    float* hb = g_hidden + ((long)b * 384 + o0) * HW + hw0;
#pragma unroll
    for (int i = 0; i < 8; i++) {
        float4 v0 = make_float4(acc[i][0], acc[i][1], acc[i][2], acc[i][3]);
        float4 v1 = make_float4(acc[i][4], acc[i][5], acc[i][6], acc[i][7]);
        *(float4*)(hb + (long)(oo + i) * HW + pp) = v0;
        *(float4*)(hb + (long)(oo + i) * HW + pp + 4) = v1;
    }
}

// ---------------------------------------------------------------------------
// Kernel 2: depthwise 3x3 (unchanged from R1), writes patched qkv layout.
// ---------------------------------------------------------------------------
__global__ __launch_bounds__(256) void dw3x3_kernel(const float* __restrict__ wdw) {
    __shared__ float smh[66 * 68];
    const int t = threadIdx.x;
    const int tix = blockIdx.x;
    const int ch = blockIdx.y;
    const int b = blockIdx.z;
    const int ty = tix >> 2, tx = tix & 3;
    const int y0 = ty * 64, x0 = tx * 64;

    const float* src = g_hidden + (long)(b * 384 + ch) * HW;
    for (int l = t; l < 66 * 66; l += 256) {
        int r = l / 66, c = l - r * 66;
        int y = y0 + r - 1, x = x0 + c - 1;
        float v = 0.f;
        if ((unsigned)y < 256u && (unsigned)x < 256u) v = src[y * IMG + x];
        smh[r * 68 + c] = v;
    }
    float w[9];
#pragma unroll
    for (int i = 0; i < 9; i++) w[i] = __ldg(wdw + ch * 9 + i);
    __syncthreads();

#pragma unroll 4
    for (int i = 0; i < 16; i++) {
        int L = t + i * 256;
        int p = L >> 6, inner = L & 63;
        int tpy = p >> 3, tpx = p & 7;
        int iy = inner >> 3, ix = inner & 7;
        int y = tpy * 8 + iy, x = tpx * 8 + ix;
        float acc = 0.f;
#pragma unroll
        for (int ky = 0; ky < 3; ky++)
#pragma unroll
            for (int kx = 0; kx < 3; kx++)
                acc += smh[(y + ky) * 68 + (x + kx)] * w[ky * 3 + kx];
        int pg = (ty * 8 + tpy) * 32 + (tx * 8 + tpx);
        g_qkv[((long)(b * 1024 + pg) * 384 + ch) * 64 + inner] = acc;
    }
}

// ---------------------------------------------------------------------------
// Kernel 3: per-patch attention. Restructured for 3 CTAs/SM:
//   bufQ    @0      [128][68]  (8704)  stride 68 -> conflict-free q f4 loads;
//                                      becomes convout in-place after phase 2,
//                                      then projbuf overlay (phase 4).
//   bufK    @8704   [128][72]  (9216)  stride-9 rows; becomes gatedT overlay.
//   psum    @17920  [4][64]    (256)
//   psq     @18176  [4][64]    (256)
// total = 18432 floats = 73728 B  -> 3 CTAs/SM (216KB)
// ---------------------------------------------------------------------------
#define SQ 68
#define S_BUFK 8704
#define S_PSUM 17920
#define S_PSQ 18176
#define SMEM2_FLOATS 18432

__global__ __launch_bounds__(256, 3) void fsas2_kernel(const float* __restrict__ w_out,
                                                       const float* __restrict__ lnw,
                                                       const float* __restrict__ lnb,
                                                       float* __restrict__ out) {
    extern __shared__ float sm[];
    float* bufQ = sm;              // [128][SQ], then convout, then projbuf
    float* bufK = sm + S_BUFK;     // [128][72], then gatedT [64][132]
    float* gatedT = bufK;
    float* projbuf = sm;           // [64][68] overlay (bufQ dead by then)
    float* psum = sm + S_PSUM;
    float* psq = sm + S_PSQ;

    const int t = threadIdx.x;
    const int pid = blockIdx.x;
    const int b = pid >> 10;
    const int patch = pid & 1023;
    const int ph = patch >> 5;
    const int pw = patch & 31;
    const int y0 = ph * 8, x0 = pw * 8;
    const int lane = t >> 6;       // 0..3
    const int pix = t & 63;

    const float* base = g_qkv + (long)pid * 384 * 64;

    // ---- Phase 1: load q (stride-68 rows) and k (stride-9 rows) ----
#pragma unroll
    for (int r = 0; r < 8; r++) {
        int idx = t + r * 256;               // 2048 f4 = 128 ch x 16 f4
        float4 v = ((const float4*)base)[idx];
        int c = idx >> 4;
        int word = (idx & 15) * 4;
        *(float4*)(bufQ + c * SQ + word) = v;
    }
#pragma unroll
    for (int r = 0; r < 8; r++) {
        int idx = t + r * 256;
        float4 v = ((const float4*)(base + 8192))[idx];
        int c = idx >> 4;
        int word = (idx & 15) * 4;
        int row = word >> 3, col = word & 7;
        float* dk = bufK + c * 72 + row * 9 + col;
        dk[0] = v.x; dk[1] = v.y; dk[2] = v.z; dk[3] = v.w;
    }
    __syncthreads();

    // ---- Phase 2: 8x8 circular conv; warp owns 16-channel band; in-place ----
    {
        const int w = t >> 5;      // warp 0..7
        const int ln = t & 31;
        const int aa = ln & 7;
        const int csub = ln >> 3;  // 0..3
#pragma unroll 1
        for (int r = 0; r < 4; r++) {
            int c = w * 16 + r * 4 + csub;
            const float* bq = bufQ + c * SQ;
            const float* bk = bufK + c * 72;
            float acc[8];
#pragma unroll
            for (int bb = 0; bb < 8; bb++) acc[bb] = 0.f;
#pragma unroll
            for (int i = 0; i < 8; i++) {
                float4 q0 = *(const float4*)(bq + i * 8);
                float4 q1 = *(const float4*)(bq + i * 8 + 4);
                float qr[8] = {q0.x, q0.y, q0.z, q0.w, q1.x, q1.y, q1.z, q1.w};
                int ka = (aa - i) & 7;
                const float* kr = bk + ka * 9;
                float kk[8];
#pragma unroll
                for (int m = 0; m < 8; m++) kk[m] = kr[m];
#pragma unroll
                for (int j = 0; j < 8; j++)
#pragma unroll
                    for (int bb = 0; bb < 8; bb++) acc[bb] += qr[j] * kk[(bb - j) & 7];
            }
            __syncwarp();          // all reads of band-channel q done before overwrite
            float* co = bufQ + c * SQ + aa * 8;
            *(float4*)(co) = make_float4(acc[0], acc[1], acc[2], acc[3]);
            *(float4*)(co + 4) = make_float4(acc[4], acc[5], acc[6], acc[7]);
        }
    }
    __syncthreads();

    // ---- Phase 3a: LayerNorm partial sums over 128 channels ----
    {
        float s = 0.f, s2 = 0.f;
#pragma unroll 1
        for (int cb = 0; cb < 32; cb++) {
            float v = bufQ[(cb * 4 + lane) * SQ + pix];
            s += v;
            s2 += v * v;
        }
        psum[lane * 64 + pix] = s;
        psq[lane * 64 + pix] = s2;
    }
    __syncthreads();

    // ---- Phase 3b: normalize, gate by v (from global), write gatedT ----
    {
        float mu = (psum[pix] + psum[64 + pix] + psum[128 + pix] + psum[192 + pix]) *
                   (1.f / 128.f);
        float ex2 = (psq[pix] + psq[64 + pix] + psq[128 + pix] + psq[192 + pix]) *
                    (1.f / 128.f);
        float var = ex2 - mu * mu;
        float rstd = rsqrtf(var + 1e-5f);
        const float* vsrc = base + 256 * 64;
#pragma unroll 8
        for (int cb = 0; cb < 32; cb++) {
            int c = cb * 4 + lane;
            float vv = __ldg(vsrc + c * 64 + pix);
            float g = (bufQ[c * SQ + pix] - mu) * rstd * __ldg(lnw + c) + __ldg(lnb + c);
            gatedT[pix * 132 + c] = g * vv;
        }
    }
    __syncthreads();

    // ---- Phase 4: projection 128 -> 64, write projbuf (overlay bufQ) ----
    {
        int o = t >> 2;
        int pl = t & 3;
        float acc[16];
#pragma unroll
        for (int pp2 = 0; pp2 < 16; pp2++) acc[pp2] = 0.f;
        const float4* wrow = (const float4*)(w_out) + o * 32;
#pragma unroll 1
        for (int cq = 0; cq < 32; cq++) {
            float4 w4 = __ldg(wrow + cq);
#pragma unroll
            for (int pp2 = 0; pp2 < 16; pp2++) {
                int p = pp2 * 4 + pl;
                float4 g4 = *(const float4*)(gatedT + p * 132 + cq * 4);
                acc[pp2] += w4.x * g4.x + w4.y * g4.y + w4.z * g4.z + w4.w * g4.w;
            }
        }
#pragma unroll
        for (int pp2 = 0; pp2 < 16; pp2++)
            projbuf[o * 68 + pp2 * 4 + pl] = acc[pp2];
    }
    __syncthreads();

    // ---- Phase 5: coalesced writeout ----
    {
        int o2 = t >> 2;
        int part = t & 3;
        float* ob = out + ((long)(b * 64 + o2) * IMG + y0) * IMG + x0;
#pragma unroll
        for (int ry = 0; ry < 2; ry++) {
            int y = part * 2 + ry;
            float4 v0 = *(const float4*)(projbuf + o2 * 68 + y * 8);
            float4 v1 = *(const float4*)(projbuf + o2 * 68 + y * 8 + 4);
            *(float4*)(ob + y * IMG) = v0;
            *(float4*)(ob + y * IMG + 4) = v1;
        }
    }
}

// ---------------------------------------------------------------------------
extern "C" void kernel_launch(void* const* d_in, const int* in_sizes, int n_in,
                              void* d_out, int out_size) {
    const float* x = (const float*)d_in[0];
    const float* w1 = (const float*)d_in[1];
    const float* wdw = (const float*)d_in[2];
    const float* wout = (const float*)d_in[3];
    const float* lnw = (const float*)d_in[4];
    const float* lnb = (const float*)d_in[5];
    float* out = (float*)d_out;

    cudaFuncSetAttribute(conv1x1_kernel, cudaFuncAttributeMaxDynamicSharedMemorySize,
                         64 * 128 * 4 + 128 * 64 * 4);
    cudaFuncSetAttribute(fsas2_kernel, cudaFuncAttributeMaxDynamicSharedMemorySize,
                         SMEM2_FLOATS * 4);

    conv1x1_kernel<<<dim3(2048, 3, 1), 256, 64 * 128 * 4 + 128 * 64 * 4>>>(x, w1);
    dw3x3_kernel<<<dim3(16, 384, 4), 256>>>(wdw);
    fsas2_kernel<<<4096, 256, SMEM2_FLOATS * 4>>>(wout, lnw, lnb, out);
}